// round 3
// baseline (speedup 1.0000x reference)
#include <cuda_runtime.h>

// TorchGrouper — warp-autonomous version.
// One warp per grid position g; transpose via warp-private smem subtiles
// (8 k-rows x 64 c). No __syncthreads in the main path -> no block-level
// barrier serialization. Output: [C,G,K] features, [4,G,K] gpf, [G] mask.

#define ZDIM 40
#define YDIM 400
#define XDIM 400
#define KK 64
#define CC 64
#define TPB 256
#define WPB 8            // warps per block
#define TROW 17          // float4 per tile row (16 data + 1 pad)

__global__ __launch_bounds__(TPB) void grouper_kernel(
    const int* __restrict__ vox,     // [N,Z,Y,X]
    const int* __restrict__ gpos,    // [G,4] (n,z,y,x)
    const float* __restrict__ feat,  // [M,C]
    const int* __restrict__ off,     // [K,4]
    float* __restrict__ out,
    int G)
{
    __shared__ float  s_gpf[4][KK];            // 1 KB, same for every g
    __shared__ float4 s_tile[WPB][8 * TROW];   // 2176 B per warp

    const int t    = threadIdx.x;
    const int wid  = t >> 5;
    const int lane = t & 31;
    const int g    = blockIdx.x * WPB + wid;
    const size_t GK = (size_t)G * KK;

    // ---- gpf lookup table (positions are integers => frac = 0) ----
    if (t < KK) {
        int4 of = reinterpret_cast<const int4*>(off)[t];
        s_gpf[0][t] = (float)of.x;
        s_gpf[1][t] = (float)of.y;
        s_gpf[2][t] = (float)of.z;
        s_gpf[3][t] = (float)of.w;
    }
    __syncthreads();   // only block barrier in the kernel

    // ---- Phase 1: 64 voxel lookups per warp (2 per lane), idx in regs ----
    const int4 gp = reinterpret_cast<const int4*>(gpos)[g];
    int idx0, idx1;
    {
        int4 of0 = reinterpret_cast<const int4*>(off)[lane];
        int4 of1 = reinterpret_cast<const int4*>(off)[lane + 32];
        int z = min(max(gp.y + of0.y, 0), ZDIM - 1);
        int y = min(max(gp.z + of0.z, 0), YDIM - 1);
        int x = min(max(gp.w + of0.w, 0), XDIM - 1);
        idx0 = __ldcs(&vox[((gp.x * ZDIM + z) * YDIM + y) * XDIM + x]);
        z = min(max(gp.y + of1.y, 0), ZDIM - 1);
        y = min(max(gp.z + of1.z, 0), YDIM - 1);
        x = min(max(gp.w + of1.w, 0), XDIM - 1);
        idx1 = __ldcs(&vox[((gp.x * ZDIM + z) * YDIM + y) * XDIM + x]);
    }
    unsigned m0 = __ballot_sync(0xffffffffu, idx0 >= 0);
    unsigned m1 = __ballot_sync(0xffffffffu, idx1 >= 0);
    if (lane == 0)
        out[(size_t)(CC + 4) * GK + g] = ((m0 | m1) == 0u) ? 1.0f : 0.0f;

    // ---- gpf output: [4,G,K], float4 along k ----
    {
        float* out_gpf = out + (size_t)CC * GK;
#pragma unroll
        for (int q = 0; q < 2; q++) {
            const int job = q * 32 + lane;   // 0..63
            const int ch  = job >> 4;        // 0..3
            const int kq  = job & 15;
            float4 v;
            v.x = s_gpf[ch][kq * 4 + 0];
            v.y = s_gpf[ch][kq * 4 + 1];
            v.z = s_gpf[ch][kq * 4 + 2];
            v.w = s_gpf[ch][kq * 4 + 3];
            __stcs(reinterpret_cast<float4*>(
                       out_gpf + (size_t)ch * GK + (size_t)g * KK + kq * 4), v);
        }
    }

    // ---- Main loop: 8 subtiles of 8 k-rows each ----
    float4* tile = s_tile[wid];
    const float* tf = reinterpret_cast<const float*>(tile);
    const float4* feat4 = reinterpret_cast<const float4*>(feat);

#pragma unroll 1
    for (int st = 0; st < 8; st++) {
        // gather: 8 rows x 16 float4 = 128 jobs, 4 per lane (batched loads)
        float4 v[4];
#pragma unroll
        for (int q = 0; q < 4; q++) {
            const int job = q * 32 + lane;
            const int r   = job >> 4;          // 0..7
            const int cq  = job & 15;
            const int kk  = st * 8 + r;
            const int ia  = __shfl_sync(0xffffffffu, idx0, kk & 31);
            const int ib  = __shfl_sync(0xffffffffu, idx1, kk & 31);
            const int idx = (kk < 32) ? ia : ib;
            v[q] = make_float4(0.f, 0.f, 0.f, 0.f);
            if (idx >= 0) v[q] = feat4[(size_t)idx * (CC / 4) + cq];
        }
#pragma unroll
        for (int q = 0; q < 4; q++) {
            const int job = q * 32 + lane;
            tile[(job >> 4) * TROW + (job & 15)] = v[q];
        }
        __syncwarp();

        // drain: 64 c x 2 float4 = 128 jobs, 4 per lane (conflict-free LDS)
#pragma unroll
        for (int q = 0; q < 4; q++) {
            const int job = q * 32 + lane;
            const int c   = job >> 1;          // 0..63
            const int kq  = job & 1;
            float4 o;
            o.x = tf[(kq * 4 + 0) * (TROW * 4) + c];
            o.y = tf[(kq * 4 + 1) * (TROW * 4) + c];
            o.z = tf[(kq * 4 + 2) * (TROW * 4) + c];
            o.w = tf[(kq * 4 + 3) * (TROW * 4) + c];
            __stcs(reinterpret_cast<float4*>(
                       out + (size_t)c * GK + (size_t)g * KK + st * 8 + kq * 4), o);
        }
        __syncwarp();
    }
}

extern "C" void kernel_launch(void* const* d_in, const int* in_sizes, int n_in,
                              void* d_out, int out_size) {
    const int*   vox  = (const int*)d_in[0];
    const int*   gpos = (const int*)d_in[1];
    const float* feat = (const float*)d_in[2];
    const int*   off  = (const int*)d_in[3];
    float* out = (float*)d_out;

    const int G = in_sizes[1] / 4;           // 30000; 30000/8 = 3750 blocks
    grouper_kernel<<<G / WPB, TPB>>>(vox, gpos, feat, off, out, G);
}

// round 5
// speedup vs baseline: 1.7534x; 1.7534x over previous
#include <cuda_runtime.h>

// TorchGrouper — round 5: block-per-g, register 4x4 transpose (FIXED
// butterfly: send complement element, keep own), fully conflict-free
// 128-bit smem path (XOR-swizzled [c][kq] tile).
// Output: [C,G,K] features, [4,G,K] gpf, [G] mask (float 1/0).

#define ZDIM 40
#define YDIM 400
#define XDIM 400
#define KK 64
#define CC 64
#define TPB 256

__global__ __launch_bounds__(TPB, 8) void grouper_kernel(
    const int* __restrict__ vox,     // [N,Z,Y,X]
    const int* __restrict__ gpos,    // [G,4]
    const float* __restrict__ feat,  // [M,C]
    const int* __restrict__ off,     // [K,4]
    float* __restrict__ out,
    int G)
{
    __shared__ int      s_idx[KK];
    __shared__ unsigned s_ball[2];
    __shared__ float4   s_tile[KK * 16];   // [c][kq] swizzled, 16 KB

    const int g    = blockIdx.x;
    const int t    = threadIdx.x;
    const int w    = t >> 5;
    const int lane = t & 31;
    const size_t GK = (size_t)G * KK;

    // ---- Phase 1: 64 voxel lookups (warps 0,1), idx -> smem ----
    if (t < KK) {
        const int4 gp = reinterpret_cast<const int4*>(gpos)[g];
        const int4 of = reinterpret_cast<const int4*>(off)[t];
        int z = min(max(gp.y + of.y, 0), ZDIM - 1);
        int y = min(max(gp.z + of.z, 0), YDIM - 1);
        int x = min(max(gp.w + of.w, 0), XDIM - 1);
        int idx = __ldcs(&vox[((gp.x * ZDIM + z) * YDIM + y) * XDIM + x]);
        s_idx[t] = idx;
        unsigned m = __ballot_sync(0xffffffffu, idx >= 0);
        if (lane == 0) s_ball[w] = m;
    }

    // ---- gpf (independent of lookups): positions are ints => frac = 0 ----
    {
        const int ch = t >> 6;         // 0..3
        const int k  = t & 63;
        __stcs(out + (size_t)(CC + ch) * GK + (size_t)g * KK + k,
               (float)off[k * 4 + ch]);
    }
    __syncthreads();

    if (t == 0)
        out[(size_t)(CC + 4) * GK + g] =
            ((s_ball[0] | s_ball[1]) == 0u) ? 1.0f : 0.0f;

    // ---- Phase 2: gather + in-register 4x4 transpose + STS.128 ----
    // lane = cq*4 + p : p = row-in-quad (0..3), cq = c-quad (0..7)
    const int p  = lane & 3;
    const int cq = lane >> 2;
    const bool p0 = (p & 1) != 0;
    const bool p1 = (p >> 1) != 0;
    const float4* feat4 = reinterpret_cast<const float4*>(feat);

#pragma unroll
    for (int j = 0; j < 4; j++) {
        const int task  = w * 4 + j;         // 0..31
        const int kq4   = task >> 1;         // k-quad index 0..15
        const int chalf = task & 1;          // c half
        const int k     = kq4 * 4 + p;
        const int c0    = chalf * 32 + cq * 4;
        const int idx   = s_idx[k];
        float4 v = make_float4(0.f, 0.f, 0.f, 0.f);
        if (idx >= 0) v = feat4[(size_t)idx * (CC / 4) + (c0 >> 2)];

        // A[p][i] = value at (k0+p, c0+i); produce D[p][i] = A[i][p].
        // Stage 1 (bfly 1, swap bit p0 <-> i0): keep a[(i1,p0)], SEND a[(i1,~p0)]
        float a0 = v.x, a1 = v.y, a2 = v.z, a3 = v.w;
        float k0_ = p0 ? a1 : a0;
        float s0_ = p0 ? a0 : a1;
        float k2_ = p0 ? a3 : a2;
        float s2_ = p0 ? a2 : a3;
        float r0_ = __shfl_xor_sync(0xffffffffu, s0_, 1);
        float r2_ = __shfl_xor_sync(0xffffffffu, s2_, 1);
        float B0 = p0 ? r0_ : k0_;
        float B1 = p0 ? k0_ : r0_;
        float B2 = p0 ? r2_ : k2_;
        float B3 = p0 ? k2_ : r2_;
        // Stage 2 (bfly 2, swap bit p1 <-> i1): keep B[(p1,i0)], SEND B[(~p1,i0)]
        float kp0 = p1 ? B2 : B0;
        float sp0 = p1 ? B0 : B2;
        float kp1 = p1 ? B3 : B1;
        float sp1 = p1 ? B1 : B3;
        float rp0 = __shfl_xor_sync(0xffffffffu, sp0, 2);
        float rp1 = __shfl_xor_sync(0xffffffffu, sp1, 2);
        float4 d;
        d.x = p1 ? rp0 : kp0;   // k0+0 at channel c0+p
        d.y = p1 ? rp1 : kp1;   // k0+1
        d.z = p1 ? kp0 : rp0;   // k0+2
        d.w = p1 ? kp1 : rp1;   // k0+3
        const int c = c0 + p;
        s_tile[c * 16 + (kq4 ^ (c & 15))] = d;   // swizzled, STS.128 CF
    }
    __syncthreads();

    // ---- Phase 3: drain, LDS.128 CF + streaming STG.128 ----
#pragma unroll
    for (int j = 0; j < 4; j++) {
        const int job = t + TPB * j;         // 0..1023
        const int c   = job >> 4;            // 0..63
        const int q   = job & 15;            // k-quad
        float4 o = s_tile[c * 16 + (q ^ (c & 15))];
        __stcs(reinterpret_cast<float4*>(
                   out + (size_t)c * GK + (size_t)g * KK + q * 4), o);
    }
}

extern "C" void kernel_launch(void* const* d_in, const int* in_sizes, int n_in,
                              void* d_out, int out_size) {
    const int*   vox  = (const int*)d_in[0];
    const int*   gpos = (const int*)d_in[1];
    const float* feat = (const float*)d_in[2];
    const int*   off  = (const int*)d_in[3];
    float* out = (float*)d_out;

    const int G = in_sizes[1] / 4;   // 30000
    grouper_kernel<<<G, TPB>>>(vox, gpos, feat, off, out, G);
}

// round 6
// speedup vs baseline: 2.0447x; 1.1661x over previous
#include <cuda_runtime.h>

// TorchGrouper — round 6: persistent blocks + software-pipelined voxel
// lookups (next-g prefetch into registers, double-buffered s_idx).
// Memory pattern identical to round 1 (proven): tile[k][c] stride-65,
// float4 gather, float4 streaming stores.
// Output: [C,G,K] features, [4,G,K] gpf, [G] mask (float 1/0).

#define ZDIM 40
#define YDIM 400
#define XDIM 400
#define KK 64
#define CC 64
#define TPB 256
#define NBLK 1184        // 148 SMs x 8 resident blocks
#define TS 65            // tile row stride (floats)

__global__ __launch_bounds__(TPB, 8) void grouper_kernel(
    const int* __restrict__ vox,     // [N,Z,Y,X]
    const int* __restrict__ gpos,    // [G,4]
    const float* __restrict__ feat,  // [M,C]
    const int* __restrict__ off,     // [K,4]
    float* __restrict__ out,
    int G)
{
    __shared__ int      s_idx[2][KK];
    __shared__ unsigned s_ball[2][2];
    __shared__ float    s_tile[KK * TS];

    const int t    = threadIdx.x;
    const int w    = t >> 5;
    const int lane = t & 31;
    const size_t GK = (size_t)G * KK;
    float* out_gpf  = out + (size_t)CC * GK;
    float* out_mask = out + (size_t)(CC + 4) * GK;
    const float4* feat4 = reinterpret_cast<const float4*>(feat);

    // loop-invariant per-thread constants
    const int gpf_ch = t >> 6;           // 0..3
    const int gpf_k  = t & 63;
    const float gpf_val = (float)off[gpf_k * 4 + gpf_ch];
    int4 of = make_int4(0, 0, 0, 0);
    if (t < KK) of = reinterpret_cast<const int4*>(off)[t];

    // ---- prologue: lookup for first g ----
    int g = blockIdx.x;
    if (t < KK) {
        const int4 gp = reinterpret_cast<const int4*>(gpos)[g];
        int z = min(max(gp.y + of.y, 0), ZDIM - 1);
        int y = min(max(gp.z + of.z, 0), YDIM - 1);
        int x = min(max(gp.w + of.w, 0), XDIM - 1);
        int idx = vox[((gp.x * ZDIM + z) * YDIM + y) * XDIM + x];
        s_idx[0][t] = idx;
        unsigned m = __ballot_sync(0xffffffffu, idx >= 0);
        if (lane == 0) s_ball[0][w] = m;
    }
    __syncthreads();

    int p = 0;
    for (; g < G; g += NBLK) {
        const int g_next = g + NBLK;
        const bool has_next = (g_next < G);

        // ---- prefetch next g's voxel lookups into registers ----
        int idxnext = -1;
        if (t < KK && has_next) {
            const int4 gp = reinterpret_cast<const int4*>(gpos)[g_next];
            int z = min(max(gp.y + of.y, 0), ZDIM - 1);
            int y = min(max(gp.z + of.z, 0), YDIM - 1);
            int x = min(max(gp.w + of.w, 0), XDIM - 1);
            idxnext = vox[((gp.x * ZDIM + z) * YDIM + y) * XDIM + x];
        }

        // ---- gather current g: feature rows -> tile[k][c] ----
#pragma unroll
        for (int j = 0; j < 4; j++) {
            const int job = t + TPB * j;     // 0..1023
            const int k   = job >> 4;        // 0..63
            const int cq  = job & 15;
            const int idx = s_idx[p][k];
            float4 v = make_float4(0.f, 0.f, 0.f, 0.f);
            if (idx >= 0) v = feat4[(size_t)idx * (CC / 4) + cq];
            float* dst = &s_tile[k * TS + cq * 4];
            dst[0] = v.x; dst[1] = v.y; dst[2] = v.z; dst[3] = v.w;
        }
        __syncthreads();

        // ---- drain: transposed float4 streaming stores ----
#pragma unroll
        for (int j = 0; j < 4; j++) {
            const int job = t + TPB * j;
            const int c   = job >> 4;        // 0..63
            const int kq  = job & 15;
            float4 v;
            v.x = s_tile[(kq * 4 + 0) * TS + c];
            v.y = s_tile[(kq * 4 + 1) * TS + c];
            v.z = s_tile[(kq * 4 + 2) * TS + c];
            v.w = s_tile[(kq * 4 + 3) * TS + c];
            __stcs(reinterpret_cast<float4*>(
                       out + (size_t)c * GK + (size_t)g * KK + kq * 4), v);
        }

        // ---- gpf + mask for current g ----
        __stcs(out_gpf + (size_t)gpf_ch * GK + (size_t)g * KK + gpf_k, gpf_val);
        if (t == 0)
            out_mask[g] = ((s_ball[p][0] | s_ball[p][1]) == 0u) ? 1.0f : 0.0f;

        // ---- publish prefetched lookups into the other buffer ----
        if (t < KK && has_next) {
            s_idx[1 - p][t] = idxnext;
            unsigned m = __ballot_sync(0xffffffffu, idxnext >= 0);
            if (lane == 0) s_ball[1 - p][w] = m;
        }
        __syncthreads();
        p ^= 1;
    }
}

extern "C" void kernel_launch(void* const* d_in, const int* in_sizes, int n_in,
                              void* d_out, int out_size) {
    const int*   vox  = (const int*)d_in[0];
    const int*   gpos = (const int*)d_in[1];
    const float* feat = (const float*)d_in[2];
    const int*   off  = (const int*)d_in[3];
    float* out = (float*)d_out;

    const int G = in_sizes[1] / 4;   // 30000
    grouper_kernel<<<NBLK, TPB>>>(vox, gpos, feat, off, out, G);
}